// round 16
// baseline (speedup 1.0000x reference)
#include <cuda_runtime.h>
#include <cuda_bf16.h>

// Problem constants
constexpr int B = 4, C = 32, H = 720, W = 720;
constexpr int HW = H * W;              // 518400
constexpr int BHW = B * HW;            // 2073600

// Tiling for fused diag+conv kernel
constexpr int TH  = 8;     // output rows per block
constexpr int TWF = 360;   // output cols per block (W/2)
constexpr int SROWS = TH + 10;   // 18 s rows (halo: d needs ±1 rows, each d row ±4 diag)
constexpr int DROWS = TH + 2;    // 10 d rows
constexpr int SW  = 368;   // smem row width (360 + 8 halo cols)
constexpr int NDIAG = TWF + DROWS - 1;  // 369 diagonals in the d tile

// Scratch (no cudaMalloc allowed)
__device__ float g_s[BHW];       // channel sum

// K1: s = sum_c x. Each thread owns 2 consecutive float4 (32B) per channel:
// warp covers 1KB contiguous per plane (better DRAM page locality), and two
// independent load chains per channel step (deeper MLP).
__global__ __launch_bounds__(256) void k_csum(const float* __restrict__ x) {
    int u = blockIdx.x * blockDim.x + threadIdx.x;     // over BHW/8 (32B units)
    if (u >= BHW / 8) return;
    int base = u * 8;                                   // element index
    int b = base / HW;
    int hw = base % HW;
    const float4* xp = reinterpret_cast<const float4*>(x + (size_t)b * C * HW + hw);

    float4 a0 = make_float4(0.f, 0.f, 0.f, 0.f);
    float4 a1 = make_float4(0.f, 0.f, 0.f, 0.f);
    #pragma unroll
    for (int c = 0; c < C; c++) {
        float4 v0 = __ldcs(&xp[(size_t)c * (HW / 4)]);
        float4 v1 = __ldcs(&xp[(size_t)c * (HW / 4) + 1]);
        a0.x += v0.x; a0.y += v0.y; a0.z += v0.z; a0.w += v0.w;
        a1.x += v1.x; a1.y += v1.y; a1.z += v1.z; a1.w += v1.w;
    }
    float4* sp = reinterpret_cast<float4*>(g_s + (size_t)b * HW + hw);
    sp[0] = a0;
    sp[1] = a1;
}

// K2 (fused): w2 reduction + 9-tap diagonal average (sliding window along the
// diagonal) + 3-tap broadcast conv.  (unchanged from best round)
__global__ __launch_bounds__(256) void k_fused(const float* __restrict__ cw,
                                               float* __restrict__ out) {
    __shared__ __align__(16) float s_sm[SROWS][SW];
    __shared__ __align__(16) float d_sm[DROWS][SW];
    __shared__ float sw[C * 3];

    int tid = threadIdx.x;
    if (tid < C * 3) {
        int o = tid / 3, kh = tid % 3;
        float acc = 0.f;
        #pragma unroll
        for (int i = 0; i < C; i++) acc += __ldg(&cw[o * (C * 3) + i * 3 + kh]);
        sw[tid] = acc;
    }

    int b  = blockIdx.z;
    int h0 = blockIdx.y * TH;
    int w0 = blockIdx.x * TWF;
    const float* sb = g_s + (size_t)b * HW;

    // Stage 1: load s tile [h0-5 .. h0+TH+4] x [w0-4 .. w0+TWF+3] (zero pad OOB)
    for (int t = tid; t < SROWS * (SW / 4); t += 256) {
        int i = t / (SW / 4);
        int v = t % (SW / 4);
        int gr = h0 - 5 + i;
        int gc = w0 - 4 + 4 * v;
        float4 val = make_float4(0.f, 0.f, 0.f, 0.f);
        if (gr >= 0 && gr < H && gc >= 0 && gc + 3 < W)
            val = *reinterpret_cast<const float4*>(sb + gr * W + gc);
        *reinterpret_cast<float4*>(&s_sm[i][4 * v]) = val;
    }
    __syncthreads();

    // Stage 2: d tile via diagonal sliding window.
    for (int t = tid; t < NDIAG; t += 256) {
        int c0 = t - (DROWS - 1);                  // -9 .. 359
        int k0 = c0 < 0 ? -c0 : 0;
        int k1 = TWF - 1 - c0;
        if (k1 > DROWS - 1) k1 = DROWS - 1;
        int cc = c0 + k0;

        float D = 0.f;
        #pragma unroll
        for (int j = 0; j < 9; j++) D += s_sm[k0 + j][cc + j];
        {
            int r = h0 - 1 + k0;
            d_sm[k0][cc] = (r >= 0 && r < H) ? D * (1.0f / 9.0f) : 0.f;
        }
        for (int k = k0 + 1; k <= k1; k++) {
            D += s_sm[k + 8][cc + 9] - s_sm[k - 1][cc];
            cc++;
            int r = h0 - 1 + k;
            d_sm[k][cc] = (r >= 0 && r < H) ? D * (1.0f / 9.0f) : 0.f;
        }
    }
    __syncthreads();

    // Stage 3: out[b,o,h,w] = sum_kh w2[o,kh] * d[h-1+kh, w], streaming stores
    for (int t = tid; t < TH * (TWF / 4); t += 256) {
        int k2 = t / (TWF / 4);
        int cf = t % (TWF / 4);
        int h  = h0 + k2;
        int wc = w0 + 4 * cf;

        float4 d0 = *reinterpret_cast<const float4*>(&d_sm[k2    ][4 * cf]);
        float4 d1 = *reinterpret_cast<const float4*>(&d_sm[k2 + 1][4 * cf]);
        float4 d2 = *reinterpret_cast<const float4*>(&d_sm[k2 + 2][4 * cf]);

        float* op = out + (size_t)b * C * HW + h * W + wc;
        #pragma unroll
        for (int o = 0; o < C; o++) {
            float a0 = sw[3 * o], a1 = sw[3 * o + 1], a2 = sw[3 * o + 2];
            float4 rv;
            rv.x = a0 * d0.x + a1 * d1.x + a2 * d2.x;
            rv.y = a0 * d0.y + a1 * d1.y + a2 * d2.y;
            rv.z = a0 * d0.z + a1 * d1.z + a2 * d2.z;
            rv.w = a0 * d0.w + a1 * d1.w + a2 * d2.w;
            __stcs(reinterpret_cast<float4*>(op + (size_t)o * HW), rv);
        }
    }
}

extern "C" void kernel_launch(void* const* d_in, const int* in_sizes, int n_in,
                              void* d_out, int out_size) {
    const float* x  = (const float*)d_in[0];   // (4,32,720,720)
    const float* cw = (const float*)d_in[1];   // (32,32,3,1)
    float* out = (float*)d_out;                // (4,32,720,720)

    {
        int n = BHW / 8;                        // 259200 32B units
        k_csum<<<(n + 255) / 256, 256>>>(x);
    }

    dim3 grid(W / TWF, H / TH, B);             // (2, 90, 4) = 720 blocks
    k_fused<<<grid, 256>>>(cw, out);
}